// round 12
// baseline (speedup 1.0000x reference)
#include <cuda_runtime.h>
#include <math.h>
#include <stdint.h>

// Problem constants
#define BB   8
#define SEQ  1024
#define DIM  768
#define NH   12
#define KG   4
#define HD   64
#define MTOT (BB*SEQ)     // 8192

// Scratch (static device globals — no runtime allocation allowed)
// All hold TF32 bit patterns unless noted.
__device__ uint32_t g_xtf  [(size_t)MTOT * DIM];       // x converted
__device__ uint32_t g_wqkv [(size_t)512 * DIM];        // w_qkv rows 0..511
__device__ uint32_t g_wv   [(size_t)DIM * DIM];
__device__ uint32_t g_wproj[(size_t)DIM * DIM];
__device__ float    g_qk   [(size_t)MTOT * 512];       // tf32 bits: q|k heads
__device__ float    g_v    [(size_t)MTOT * DIM];       // tf32 bits
__device__ float    g_ctx  [(size_t)MTOT * DIM];       // tf32 bits (attn out)
__device__ float    g_gl   [(size_t)BB * KG * SEQ * SEQ]; // fp32 raw logits

// ---------------------------------------------------------------------------
// TF32 / cp.async helpers
// ---------------------------------------------------------------------------
__device__ __forceinline__ uint32_t f2tf(float x) {
    uint32_t r;
    asm("cvt.rna.tf32.f32 %0, %1;" : "=r"(r) : "f"(x));
    return r;
}

__device__ __forceinline__ void mma_tf32(float* d, const uint32_t* a, const uint32_t* b) {
    asm volatile(
        "mma.sync.aligned.m16n8k8.row.col.f32.tf32.tf32.f32 "
        "{%0,%1,%2,%3}, {%4,%5,%6,%7}, {%8,%9}, {%0,%1,%2,%3};"
        : "+f"(d[0]), "+f"(d[1]), "+f"(d[2]), "+f"(d[3])
        : "r"(a[0]), "r"(a[1]), "r"(a[2]), "r"(a[3]), "r"(b[0]), "r"(b[1]));
}

__device__ __forceinline__ void cp16(uint32_t smem_dst, const void* gsrc) {
    asm volatile("cp.async.cg.shared.global [%0], [%1], 16;"
                 :: "r"(smem_dst), "l"(gsrc));
}
__device__ __forceinline__ void cp_commit() {
    asm volatile("cp.async.commit_group;");
}
__device__ __forceinline__ void cp_wait_all() {
    asm volatile("cp.async.wait_group 0;");
}
__device__ __forceinline__ void cp_wait1() {
    asm volatile("cp.async.wait_group 1;");
}
__device__ __forceinline__ void bar_named(int id, int nthreads) {
    asm volatile("bar.sync %0, %1;" :: "r"(id), "r"(nthreads) : "memory");
}

// ---------------------------------------------------------------------------
// Elementwise fp32 -> tf32-bits conversion (grid-stride, float4)
// ---------------------------------------------------------------------------
__global__ void cvt_tf32_k(const float* __restrict__ in, uint32_t* __restrict__ out, int n)
{
    for (int i = (blockIdx.x * blockDim.x + threadIdx.x) * 4; i < n;
         i += gridDim.x * blockDim.x * 4) {
        float4 v = *(const float4*)(in + i);
        uint4 o;
        o.x = f2tf(v.x); o.y = f2tf(v.y); o.z = f2tf(v.z); o.w = f2tf(v.w);
        *(uint4*)(out + i) = o;
    }
}

// ---------------------------------------------------------------------------
// Pipelined TF32 GEMM: C[M,NC] = A[M,768] @ W[NC,768]^T (+bias).
// Inputs are tf32 bit patterns. 2-stage cp.async double buffer.
// Dynamic smem: 2 stages x (As + Ws) = 2 * 2 * 128*GS_STR words.
// ---------------------------------------------------------------------------
#define GS_STR 36
#define GEMM_STAGE_W (128 * GS_STR)                 // words per buffer
#define GEMM_SMEM_W  (4 * GEMM_STAGE_W)             // As0,Ws0,As1,Ws1
#define GEMM_SMEM_B  (GEMM_SMEM_W * 4)

template<int NC, bool OUT_TF32, bool BIAS>
__global__ void __launch_bounds__(256, 2) tf32_gemm_pipe(const uint32_t* __restrict__ A,
                                                         const uint32_t* __restrict__ W,
                                                         const float* __restrict__ bias,
                                                         float* __restrict__ C)
{
    extern __shared__ uint32_t smg[];
    // layout: stage s: As at smg + s*2*STAGE, Ws at smg + s*2*STAGE + STAGE
    const int m0  = blockIdx.y * 128;
    const int n0  = blockIdx.x * 128;
    const int tid = threadIdx.x;
    const int lane = tid & 31;
    const int warp = tid >> 5;
    const int warp_m = warp >> 2;
    const int warp_n = warp & 3;
    const int qd = lane >> 2;
    const int qq = lane & 3;

    const int lr = tid >> 1;
    const int lc = (tid & 1) * 16;

    const uint32_t* Ap = A + (size_t)(m0 + lr) * DIM + lc;
    const uint32_t* Wp = W + (size_t)(n0 + lr) * DIM + lc;
    const uint32_t baseA = (uint32_t)__cvta_generic_to_shared(smg);
    const uint32_t slotOff = (uint32_t)(lr * GS_STR + lc) * 4;

    float acc[4][4][4];
#pragma unroll
    for (int mf = 0; mf < 4; mf++)
#pragma unroll
        for (int nf = 0; nf < 4; nf++)
#pragma unroll
            for (int c = 0; c < 4; c++) acc[mf][nf][c] = 0.f;

    auto issue = [&](int s, int k0) {
        const uint32_t aOff = baseA + (uint32_t)(s * 2 * GEMM_STAGE_W) * 4;
        const uint32_t wOff = aOff + (uint32_t)GEMM_STAGE_W * 4;
#pragma unroll
        for (int i = 0; i < 4; i++) {
            cp16(aOff + slotOff + i * 16, Ap + k0 + i * 4);
            cp16(wOff + slotOff + i * 16, Wp + k0 + i * 4);
        }
        cp_commit();
    };

    issue(0, 0);
    const int NIT = DIM / 32;   // 24
    for (int it = 0; it < NIT; it++) {
        const int s = it & 1;
        if (it + 1 < NIT) { issue(s ^ 1, (it + 1) * 32); cp_wait1(); }
        else cp_wait_all();
        __syncthreads();

        const uint32_t* Asx = smg + s * 2 * GEMM_STAGE_W;
        const uint32_t* Wsx = Asx + GEMM_STAGE_W;
#pragma unroll
        for (int kk = 0; kk < 32; kk += 8) {
            uint32_t a[4][4];
#pragma unroll
            for (int mf = 0; mf < 4; mf++) {
                const int base = warp_m * 64 + mf * 16 + qd;
                a[mf][0] = Asx[base * GS_STR + kk + qq];
                a[mf][1] = Asx[(base + 8) * GS_STR + kk + qq];
                a[mf][2] = Asx[base * GS_STR + kk + qq + 4];
                a[mf][3] = Asx[(base + 8) * GS_STR + kk + qq + 4];
            }
#pragma unroll
            for (int nf = 0; nf < 4; nf++) {
                const int col = warp_n * 32 + nf * 8 + qd;
                uint32_t bfr[2];
                bfr[0] = Wsx[col * GS_STR + kk + qq];
                bfr[1] = Wsx[col * GS_STR + kk + qq + 4];
#pragma unroll
                for (int mf = 0; mf < 4; mf++)
                    mma_tf32(acc[mf][nf], a[mf], bfr);
            }
        }
        __syncthreads();   // stage s reads done -> refillable next iter
    }

#pragma unroll
    for (int mf = 0; mf < 4; mf++) {
        const int row0 = m0 + warp_m * 64 + mf * 16 + qd;
        const int row1 = row0 + 8;
#pragma unroll
        for (int nf = 0; nf < 4; nf++) {
            const int col = n0 + warp_n * 32 + nf * 8 + 2 * qq;
            float2 o0, o1;
            o0.x = acc[mf][nf][0]; o0.y = acc[mf][nf][1];
            o1.x = acc[mf][nf][2]; o1.y = acc[mf][nf][3];
            if (BIAS) {
                const float2 bv = *(const float2*)&bias[col];
                o0.x += bv.x; o0.y += bv.y;
                o1.x += bv.x; o1.y += bv.y;
            }
            if (OUT_TF32) {
                o0.x = __uint_as_float(f2tf(o0.x)); o0.y = __uint_as_float(f2tf(o0.y));
                o1.x = __uint_as_float(f2tf(o1.x)); o1.y = __uint_as_float(f2tf(o1.y));
            }
            *(float2*)&C[(size_t)row0 * NC + col] = o0;
            *(float2*)&C[(size_t)row1 * NC + col] = o1;
        }
    }
}

// ---------------------------------------------------------------------------
// Kernel A: global logits gl[i,j] = q_kh[i].k_kh[j], K=64. Full-K cp.async
// load, then straight MMA. Dynamic smem.
// ---------------------------------------------------------------------------
#define GL_STR 68
#define GL_BUF_W (128 * GL_STR)
#define GL_SMEM_B (2 * GL_BUF_W * 4)

__global__ void __launch_bounds__(256, 2) gl_gemm(const float* __restrict__ QK,
                                                  float* __restrict__ GL)
{
    extern __shared__ uint32_t smgl[];
    uint32_t* As = smgl;
    uint32_t* Ws = smgl + GL_BUF_W;

    const int b  = blockIdx.z >> 2;
    const int kh = blockIdx.z & 3;
    const int m0 = blockIdx.y * 128;
    const int n0 = blockIdx.x * 128;
    const int tid = threadIdx.x;
    const int lane = tid & 31;
    const int warp = tid >> 5;
    const int warp_m = warp >> 2;
    const int warp_n = warp & 3;
    const int qd = lane >> 2;
    const int qq = lane & 3;

    const int lr = tid >> 1;
    const int lc = (tid & 1) * 32;

    const uint32_t* Ap = (const uint32_t*)QK + (size_t)(b * SEQ + m0 + lr) * 512 + kh * HD + lc;
    const uint32_t* Wp = (const uint32_t*)QK + (size_t)(b * SEQ + n0 + lr) * 512 + 256 + kh * HD + lc;
    const uint32_t AsA = (uint32_t)__cvta_generic_to_shared(As) + (uint32_t)(lr * GL_STR + lc) * 4;
    const uint32_t WsA = (uint32_t)__cvta_generic_to_shared(Ws) + (uint32_t)(lr * GL_STR + lc) * 4;

#pragma unroll
    for (int i = 0; i < 8; i++) {
        cp16(AsA + i * 16, Ap + i * 4);
        cp16(WsA + i * 16, Wp + i * 4);
    }
    cp_commit();

    float acc[4][4][4];
#pragma unroll
    for (int mf = 0; mf < 4; mf++)
#pragma unroll
        for (int nf = 0; nf < 4; nf++)
#pragma unroll
            for (int c = 0; c < 4; c++) acc[mf][nf][c] = 0.f;

    cp_wait_all();
    __syncthreads();

#pragma unroll
    for (int kk = 0; kk < HD; kk += 8) {
        uint32_t a[4][4];
#pragma unroll
        for (int mf = 0; mf < 4; mf++) {
            const int base = warp_m * 64 + mf * 16 + qd;
            a[mf][0] = As[base * GL_STR + kk + qq];
            a[mf][1] = As[(base + 8) * GL_STR + kk + qq];
            a[mf][2] = As[base * GL_STR + kk + qq + 4];
            a[mf][3] = As[(base + 8) * GL_STR + kk + qq + 4];
        }
#pragma unroll
        for (int nf = 0; nf < 4; nf++) {
            const int col = warp_n * 32 + nf * 8 + qd;
            uint32_t bfr[2];
            bfr[0] = Ws[col * GL_STR + kk + qq];
            bfr[1] = Ws[col * GL_STR + kk + qq + 4];
#pragma unroll
            for (int mf = 0; mf < 4; mf++)
                mma_tf32(acc[mf][nf], a[mf], bfr);
        }
    }

    float* Cp = GL + (size_t)blockIdx.z * SEQ * SEQ;
#pragma unroll
    for (int mf = 0; mf < 4; mf++) {
        const int row0 = m0 + warp_m * 64 + mf * 16 + qd;
        const int row1 = row0 + 8;
#pragma unroll
        for (int nf = 0; nf < 4; nf++) {
            const int col = n0 + warp_n * 32 + nf * 8 + 2 * qq;
            float2 o0, o1;
            o0.x = acc[mf][nf][0]; o0.y = acc[mf][nf][1];
            o1.x = acc[mf][nf][2]; o1.y = acc[mf][nf][3];
            *(float2*)&Cp[(size_t)row0 * SEQ + col] = o0;
            *(float2*)&Cp[(size_t)row1 * SEQ + col] = o1;
        }
    }
}

// ---------------------------------------------------------------------------
// Kernel B: mix + softmax + AV. 2 heads per CTA (256 threads, 2 CTAs/SM).
// Register-resident P (k-lane-permuted AV MMA). Epilogue writes tf32 bits.
// ---------------------------------------------------------------------------
#define HPC    2
#define SG_STR 72
#define SG_K   (64 * SG_STR)
#define VS_STR 68

__global__ void __launch_bounds__(256, 2) fish_mix_attn(const float* __restrict__ mixl,
                                                        const float* __restrict__ GL,
                                                        float* __restrict__ ctx)
{
    extern __shared__ float sm[];
    float* Sg    = sm;                          // [4k][64][SG_STR], shared by heads
    float* VsAll = Sg + 4 * SG_K;               // [2 heads][64][VS_STR]

    const int i0   = blockIdx.x * 64;
    const int b    = blockIdx.z;
    const int tid  = threadIdx.x;
    const int hh   = tid >> 7;
    const int t    = tid & 127;
    const int h    = blockIdx.y * HPC + hh;
    const int lane = tid & 31;
    const int w4   = t >> 5;
    const int qd   = lane >> 2;
    const int qq   = lane & 3;
    const int bar_id = hh + 1;

    const int row0 = 16 * w4 + qd;
    const int row1 = row0 + 8;

    float* Vs = VsAll + hh * 64 * VS_STR;

    const int gc = (tid & 15) * 4;
    const int gr = tid >> 4;
    const int vc = (t & 15) * 4;
    const int vr = t >> 4;
    const uint32_t SgA = (uint32_t)__cvta_generic_to_shared(Sg);
    const uint32_t VsA = (uint32_t)__cvta_generic_to_shared(Vs);

    // Prologue: group1 = Sg(0) + Vlow(0); group2 = Vhigh(0)
#pragma unroll
    for (int i = 0; i < 16; i++) {
        const int r = gr + 16 * i;
        const int k = r >> 6, rr = r & 63;
        cp16(SgA + (uint32_t)((k * 64 + rr) * SG_STR + gc) * 4,
             &GL[((size_t)(b * KG + k) * SEQ + i0 + rr) * SEQ + 0 + gc]);
    }
#pragma unroll
    for (int i = 0; i < 4; i++) {
        const int r = vr + 8 * i;
        cp16(VsA + (uint32_t)(r * VS_STR + vc) * 4,
             &g_v[((size_t)(b * SEQ + 0 + r)) * DIM + h * HD + vc]);
    }
    cp_commit();
#pragma unroll
    for (int i = 0; i < 4; i++) {
        const int r = 32 + vr + 8 * i;
        cp16(VsA + (uint32_t)(r * VS_STR + vc) * 4,
             &g_v[((size_t)(b * SEQ + 0 + r)) * DIM + h * HD + vc]);
    }
    cp_commit();

    // mixw = softmax(mix_logits[h,:]) * HEAD_DIM^-0.5
    float ml0 = mixl[h * KG + 0], ml1 = mixl[h * KG + 1];
    float ml2 = mixl[h * KG + 2], ml3 = mixl[h * KG + 3];
    float mm = fmaxf(fmaxf(ml0, ml1), fmaxf(ml2, ml3));
    float e0 = expf(ml0 - mm), e1 = expf(ml1 - mm);
    float e2 = expf(ml2 - mm), e3 = expf(ml3 - mm);
    float inv_es = 0.125f / (e0 + e1 + e2 + e3);
    const float mw0 = e0 * inv_es, mw1 = e1 * inv_es;
    const float mw2 = e2 * inv_es, mw3 = e3 * inv_es;

    float O[8][4];
#pragma unroll
    for (int nt = 0; nt < 8; nt++)
#pragma unroll
        for (int c = 0; c < 4; c++) O[nt][c] = 0.f;
    float m_0 = -INFINITY, m_1 = -INFINITY, l_0 = 0.f, l_1 = 0.f;

    const uint32_t* Vsu = (const uint32_t*)Vs;
    const float* mixbase = Sg + row0 * SG_STR + 2 * qq;

    for (int j0 = 0; j0 < SEQ; j0 += 64) {
        const bool more = (j0 + 64 < SEQ);

        cp_wait1();
        __syncthreads();

        // ---- mix ----
        float S[8][4];
#pragma unroll
        for (int nt = 0; nt < 8; nt++) {
            const float* p = mixbase + nt * 8;
            float2 a0 = *(const float2*)(p);
            float2 a1 = *(const float2*)(p + 8 * SG_STR);
            float2 b0 = *(const float2*)(p + SG_K);
            float2 b1 = *(const float2*)(p + SG_K + 8 * SG_STR);
            float2 c0 = *(const float2*)(p + 2 * SG_K);
            float2 c1 = *(const float2*)(p + 2 * SG_K + 8 * SG_STR);
            float2 d0 = *(const float2*)(p + 3 * SG_K);
            float2 d1 = *(const float2*)(p + 3 * SG_K + 8 * SG_STR);
            S[nt][0] = mw0 * a0.x + mw1 * b0.x + mw2 * c0.x + mw3 * d0.x;
            S[nt][1] = mw0 * a0.y + mw1 * b0.y + mw2 * c0.y + mw3 * d0.y;
            S[nt][2] = mw0 * a1.x + mw1 * b1.x + mw2 * c1.x + mw3 * d1.x;
            S[nt][3] = mw0 * a1.y + mw1 * b1.y + mw2 * c1.y + mw3 * d1.y;
        }
        __syncthreads();

        if (more) {
#pragma unroll
            for (int i = 0; i < 16; i++) {
                const int r = gr + 16 * i;
                const int k = r >> 6, rr = r & 63;
                cp16(SgA + (uint32_t)((k * 64 + rr) * SG_STR + gc) * 4,
                     &GL[((size_t)(b * KG + k) * SEQ + i0 + rr) * SEQ + j0 + 64 + gc]);
            }
            cp_commit();
        }

        // ---- warp-local online softmax ----
        float mx0 = fmaxf(S[0][0], S[0][1]), mx1 = fmaxf(S[0][2], S[0][3]);
#pragma unroll
        for (int nt = 1; nt < 8; nt++) {
            mx0 = fmaxf(mx0, fmaxf(S[nt][0], S[nt][1]));
            mx1 = fmaxf(mx1, fmaxf(S[nt][2], S[nt][3]));
        }
        mx0 = fmaxf(mx0, __shfl_xor_sync(0xffffffffu, mx0, 1));
        mx0 = fmaxf(mx0, __shfl_xor_sync(0xffffffffu, mx0, 2));
        mx1 = fmaxf(mx1, __shfl_xor_sync(0xffffffffu, mx1, 1));
        mx1 = fmaxf(mx1, __shfl_xor_sync(0xffffffffu, mx1, 2));
        const float mn0 = fmaxf(m_0, mx0), mn1 = fmaxf(m_1, mx1);
        const float corr0 = __expf(m_0 - mn0), corr1 = __expf(m_1 - mn1);
        m_0 = mn0; m_1 = mn1;

        uint32_t P[8][4];
        float rs0 = 0.f, rs1 = 0.f;
#pragma unroll
        for (int nt = 0; nt < 8; nt++) {
            const float p0 = __expf(S[nt][0] - mn0);
            const float p1 = __expf(S[nt][1] - mn0);
            const float p2 = __expf(S[nt][2] - mn1);
            const float p3 = __expf(S[nt][3] - mn1);
            rs0 += p0 + p1; rs1 += p2 + p3;
            P[nt][0] = f2tf(p0); P[nt][1] = f2tf(p2);
            P[nt][2] = f2tf(p1); P[nt][3] = f2tf(p3);
            O[nt][0] *= corr0; O[nt][1] *= corr0;
            O[nt][2] *= corr1; O[nt][3] *= corr1;
        }
        rs0 += __shfl_xor_sync(0xffffffffu, rs0, 1);
        rs0 += __shfl_xor_sync(0xffffffffu, rs0, 2);
        rs1 += __shfl_xor_sync(0xffffffffu, rs1, 1);
        rs1 += __shfl_xor_sync(0xffffffffu, rs1, 2);
        l_0 = l_0 * corr0 + rs0;
        l_1 = l_1 * corr1 + rs1;

        // ---- O += P V, low half ----
#pragma unroll
        for (int kg = 0; kg < 4; kg++) {
            const int jr = kg * 8 + 2 * qq;
#pragma unroll
            for (int nt = 0; nt < 8; nt++) {
                const int d = nt * 8 + qd;
                uint32_t bf[2];
                bf[0] = Vsu[jr * VS_STR + d];
                bf[1] = Vsu[(jr + 1) * VS_STR + d];
                mma_tf32(O[nt], P[kg], bf);
            }
        }

        if (more) cp_wait1(); else cp_wait_all();
        bar_named(bar_id, 128);
        if (more) {
#pragma unroll
            for (int i = 0; i < 4; i++) {
                const int r = vr + 8 * i;
                cp16(VsA + (uint32_t)(r * VS_STR + vc) * 4,
                     &g_v[((size_t)(b * SEQ + j0 + 64 + r)) * DIM + h * HD + vc]);
            }
            cp_commit();
        }

        // ---- O += P V, high half ----
#pragma unroll
        for (int kg = 4; kg < 8; kg++) {
            const int jr = kg * 8 + 2 * qq;
#pragma unroll
            for (int nt = 0; nt < 8; nt++) {
                const int d = nt * 8 + qd;
                uint32_t bf[2];
                bf[0] = Vsu[jr * VS_STR + d];
                bf[1] = Vsu[(jr + 1) * VS_STR + d];
                mma_tf32(O[nt], P[kg], bf);
            }
        }

        bar_named(bar_id, 128);
        if (more) {
#pragma unroll
            for (int i = 0; i < 4; i++) {
                const int r = 32 + vr + 8 * i;
                cp16(VsA + (uint32_t)(r * VS_STR + vc) * 4,
                     &g_v[((size_t)(b * SEQ + j0 + 64 + r)) * DIM + h * HD + vc]);
            }
            cp_commit();
        }
    }

    // Epilogue: normalize, write ctx as TF32 bits (proj GEMM consumes directly)
    const float inv0 = 1.f / l_0, inv1 = 1.f / l_1;
    const size_t r0off = ((size_t)(b * SEQ + i0 + row0)) * DIM + h * HD;
    const size_t r1off = ((size_t)(b * SEQ + i0 + row1)) * DIM + h * HD;
#pragma unroll
    for (int nt = 0; nt < 8; nt++) {
        const int col = nt * 8 + 2 * qq;
        uint2 o0, o1;
        o0.x = f2tf(O[nt][0] * inv0); o0.y = f2tf(O[nt][1] * inv0);
        o1.x = f2tf(O[nt][2] * inv1); o1.y = f2tf(O[nt][3] * inv1);
        *(uint2*)&ctx[r0off + col] = o0;
        *(uint2*)&ctx[r1off + col] = o1;
    }
}

// ---------------------------------------------------------------------------
// Launch
// ---------------------------------------------------------------------------
extern "C" void kernel_launch(void* const* d_in, const int* in_sizes, int n_in,
                              void* d_out, int out_size)
{
    const float* x      = (const float*)d_in[0];
    const float* w_qkv  = (const float*)d_in[1];
    const float* mixl   = (const float*)d_in[2];
    const float* w_v    = (const float*)d_in[3];
    const float* w_proj = (const float*)d_in[4];
    const float* b_proj = (const float*)d_in[5];
    float* out = (float*)d_out;

    uint32_t *xtf, *wqkv, *wv, *wproj;
    float *qk, *v, *ctx, *gl;
    cudaGetSymbolAddress((void**)&xtf,   g_xtf);
    cudaGetSymbolAddress((void**)&wqkv,  g_wqkv);
    cudaGetSymbolAddress((void**)&wv,    g_wv);
    cudaGetSymbolAddress((void**)&wproj, g_wproj);
    cudaGetSymbolAddress((void**)&qk,  g_qk);
    cudaGetSymbolAddress((void**)&v,   g_v);
    cudaGetSymbolAddress((void**)&ctx, g_ctx);
    cudaGetSymbolAddress((void**)&gl,  g_gl);

    const int attn_smem = (4 * SG_K + HPC * 64 * VS_STR) * (int)sizeof(float);
    cudaFuncSetAttribute(fish_mix_attn, cudaFuncAttributeMaxDynamicSharedMemorySize, attn_smem);
    cudaFuncSetAttribute(tf32_gemm_pipe<512, true, false>,
                         cudaFuncAttributeMaxDynamicSharedMemorySize, GEMM_SMEM_B);
    cudaFuncSetAttribute(tf32_gemm_pipe<768, true, false>,
                         cudaFuncAttributeMaxDynamicSharedMemorySize, GEMM_SMEM_B);
    cudaFuncSetAttribute(tf32_gemm_pipe<768, false, true>,
                         cudaFuncAttributeMaxDynamicSharedMemorySize, GEMM_SMEM_B);
    cudaFuncSetAttribute(gl_gemm, cudaFuncAttributeMaxDynamicSharedMemorySize, GL_SMEM_B);

    // 0) convert GEMM inputs to tf32 bits
    cvt_tf32_k<<<512, 256>>>(x, xtf, MTOT * DIM);
    cvt_tf32_k<<<256, 256>>>(w_qkv, wqkv, 512 * DIM);
    cvt_tf32_k<<<256, 256>>>(w_v, wv, DIM * DIM);
    cvt_tf32_k<<<256, 256>>>(w_proj, wproj, DIM * DIM);

    // 1) qk = x @ w_qkv[0:512]^T  -> tf32 bits
    tf32_gemm_pipe<512, true, false><<<dim3(4, 64), 256, GEMM_SMEM_B>>>(xtf, wqkv, nullptr, qk);
    // 2) v = x @ w_v^T            -> tf32 bits
    tf32_gemm_pipe<768, true, false><<<dim3(6, 64), 256, GEMM_SMEM_B>>>(xtf, wv, nullptr, v);
    // A) global logits per (b, k-head)
    gl_gemm<<<dim3(8, 8, BB * KG), 256, GL_SMEM_B>>>(qk, gl);
    // B) mix + softmax + AV (writes ctx as tf32 bits)
    fish_mix_attn<<<dim3(SEQ / 64, NH / HPC, BB), HPC * 128, attn_smem>>>(mixl, gl, ctx);
    // 4) out = ctx @ w_proj^T + b_proj (fp32 out)
    tf32_gemm_pipe<768, false, true><<<dim3(6, 64), 256, GEMM_SMEM_B>>>((const uint32_t*)ctx, wproj, b_proj, out);
}

// round 13
// speedup vs baseline: 1.0912x; 1.0912x over previous
#include <cuda_runtime.h>
#include <math.h>
#include <stdint.h>

// Problem constants
#define BB   8
#define SEQ  1024
#define DIM  768
#define NH   12
#define KG   4
#define HD   64
#define MTOT (BB*SEQ)     // 8192

// Scratch (static device globals — no runtime allocation allowed)
__device__ float g_qk [(size_t)MTOT * 512];            // tf32 bits: q|k heads
__device__ float g_vt [(size_t)BB * NH * HD * SEQ];    // tf32 bits, TRANSPOSED [b,h,d,j]
__device__ float g_ctx[(size_t)MTOT * DIM];            // fp32 attn out
__device__ float g_gl [(size_t)BB * KG * SEQ * SEQ];   // fp32 raw logits

// ---------------------------------------------------------------------------
// TF32 / cp.async helpers
// ---------------------------------------------------------------------------
__device__ __forceinline__ uint32_t f2tf(float x) {
    uint32_t r;
    asm("cvt.rna.tf32.f32 %0, %1;" : "=r"(r) : "f"(x));
    return r;
}

__device__ __forceinline__ void mma_tf32(float* d, const uint32_t* a, const uint32_t* b) {
    asm volatile(
        "mma.sync.aligned.m16n8k8.row.col.f32.tf32.tf32.f32 "
        "{%0,%1,%2,%3}, {%4,%5,%6,%7}, {%8,%9}, {%0,%1,%2,%3};"
        : "+f"(d[0]), "+f"(d[1]), "+f"(d[2]), "+f"(d[3])
        : "r"(a[0]), "r"(a[1]), "r"(a[2]), "r"(a[3]), "r"(b[0]), "r"(b[1]));
}

__device__ __forceinline__ void cp16(uint32_t smem_dst, const void* gsrc) {
    asm volatile("cp.async.cg.shared.global [%0], [%1], 16;"
                 :: "r"(smem_dst), "l"(gsrc));
}
__device__ __forceinline__ void cp_commit() {
    asm volatile("cp.async.commit_group;");
}
__device__ __forceinline__ void cp_wait_all() {
    asm volatile("cp.async.wait_group 0;");
}
__device__ __forceinline__ void cp_wait1() {
    asm volatile("cp.async.wait_group 1;");
}
__device__ __forceinline__ void bar_named(int id, int nthreads) {
    asm volatile("bar.sync %0, %1;" :: "r"(id), "r"(nthreads) : "memory");
}

// ---------------------------------------------------------------------------
// TF32 tensor-core GEMM (R9 style): C[M,NC] = A[M,768] @ W[NC,768]^T (+bias)
// fp32 global loads, cvt at smem store, register prefetch.
// OUTMODE: 0 = fp32, 1 = tf32 bits, 2 = tf32 bits into transposed V layout.
// ---------------------------------------------------------------------------
#define GS_STR 36

template<int NC, int OUTMODE, bool BIAS>
__global__ void __launch_bounds__(256, 2) tf32_gemm_nt(const float* __restrict__ A,
                                                       const float* __restrict__ W,
                                                       const float* __restrict__ bias,
                                                       float* __restrict__ C)
{
    __shared__ uint32_t As[128 * GS_STR];
    __shared__ uint32_t Ws[128 * GS_STR];

    const int m0  = blockIdx.y * 128;
    const int n0  = blockIdx.x * 128;
    const int tid = threadIdx.x;
    const int lane = tid & 31;
    const int warp = tid >> 5;
    const int warp_m = warp >> 2;
    const int warp_n = warp & 3;
    const int qd = lane >> 2;
    const int qq = lane & 3;

    const int lr = tid >> 1;
    const int lc = (tid & 1) * 16;

    const float* Ap = A + (size_t)(m0 + lr) * DIM + lc;
    const float* Wp = W + (size_t)(n0 + lr) * DIM + lc;
    uint32_t* Asd = &As[lr * GS_STR + lc];
    uint32_t* Wsd = &Ws[lr * GS_STR + lc];

    float acc[4][4][4];
#pragma unroll
    for (int mf = 0; mf < 4; mf++)
#pragma unroll
        for (int nf = 0; nf < 4; nf++)
#pragma unroll
            for (int c = 0; c < 4; c++) acc[mf][nf][c] = 0.f;

    float4 av[4], wv[4];
#pragma unroll
    for (int i = 0; i < 4; i++) {
        av[i] = *(const float4*)(Ap + i * 4);
        wv[i] = *(const float4*)(Wp + i * 4);
    }

    for (int k0 = 0; k0 < DIM; k0 += 32) {
        __syncthreads();
#pragma unroll
        for (int i = 0; i < 4; i++) {
            uint4 at, wt;
            at.x = f2tf(av[i].x); at.y = f2tf(av[i].y);
            at.z = f2tf(av[i].z); at.w = f2tf(av[i].w);
            wt.x = f2tf(wv[i].x); wt.y = f2tf(wv[i].y);
            wt.z = f2tf(wv[i].z); wt.w = f2tf(wv[i].w);
            *(uint4*)(Asd + i * 4) = at;
            *(uint4*)(Wsd + i * 4) = wt;
        }
        __syncthreads();

        if (k0 + 32 < DIM) {
#pragma unroll
            for (int i = 0; i < 4; i++) {
                av[i] = *(const float4*)(Ap + k0 + 32 + i * 4);
                wv[i] = *(const float4*)(Wp + k0 + 32 + i * 4);
            }
        }

#pragma unroll
        for (int kk = 0; kk < 32; kk += 8) {
            uint32_t a[4][4];
#pragma unroll
            for (int mf = 0; mf < 4; mf++) {
                const int base = warp_m * 64 + mf * 16 + qd;
                a[mf][0] = As[base * GS_STR + kk + qq];
                a[mf][1] = As[(base + 8) * GS_STR + kk + qq];
                a[mf][2] = As[base * GS_STR + kk + qq + 4];
                a[mf][3] = As[(base + 8) * GS_STR + kk + qq + 4];
            }
#pragma unroll
            for (int nf = 0; nf < 4; nf++) {
                const int col = warp_n * 32 + nf * 8 + qd;
                uint32_t bfr[2];
                bfr[0] = Ws[col * GS_STR + kk + qq];
                bfr[1] = Ws[col * GS_STR + kk + qq + 4];
#pragma unroll
                for (int mf = 0; mf < 4; mf++)
                    mma_tf32(acc[mf][nf], a[mf], bfr);
            }
        }
    }

#pragma unroll
    for (int mf = 0; mf < 4; mf++) {
        const int row0 = m0 + warp_m * 64 + mf * 16 + qd;
        const int row1 = row0 + 8;
#pragma unroll
        for (int nf = 0; nf < 4; nf++) {
            const int col = n0 + warp_n * 32 + nf * 8 + 2 * qq;
            float2 o0, o1;
            o0.x = acc[mf][nf][0]; o0.y = acc[mf][nf][1];
            o1.x = acc[mf][nf][2]; o1.y = acc[mf][nf][3];
            if (BIAS) {
                const float2 bv = *(const float2*)&bias[col];
                o0.x += bv.x; o0.y += bv.y;
                o1.x += bv.x; o1.y += bv.y;
            }
            if (OUTMODE == 2) {
                // transposed V store: row=(b*SEQ+j), col=(h*64+d)
                const int b0 = row0 >> 10, j0r = row0 & 1023;
                const int b1 = row1 >> 10, j1r = row1 & 1023;
                const int hh = col >> 6, dd = col & 63;
                float* vt0 = C + ((size_t)(b0 * NH + hh) * HD + dd) * SEQ;
                float* vt1 = C + ((size_t)(b1 * NH + hh) * HD + dd) * SEQ;
                vt0[j0r]       = __uint_as_float(f2tf(o0.x));
                vt0[SEQ + j0r] = __uint_as_float(f2tf(o0.y));
                vt1[j1r]       = __uint_as_float(f2tf(o1.x));
                vt1[SEQ + j1r] = __uint_as_float(f2tf(o1.y));
            } else {
                if (OUTMODE == 1) {
                    o0.x = __uint_as_float(f2tf(o0.x)); o0.y = __uint_as_float(f2tf(o0.y));
                    o1.x = __uint_as_float(f2tf(o1.x)); o1.y = __uint_as_float(f2tf(o1.y));
                }
                *(float2*)&C[(size_t)row0 * NC + col] = o0;
                *(float2*)&C[(size_t)row1 * NC + col] = o1;
            }
        }
    }
}

// ---------------------------------------------------------------------------
// Kernel A: global logits. For (b, kh): gl[i,j] = q_kh[i].k_kh[j], K=64. (R9)
// ---------------------------------------------------------------------------
__global__ void __launch_bounds__(256, 2) gl_gemm(const float* __restrict__ QK,
                                                  float* __restrict__ GL)
{
    __shared__ uint32_t As[128 * GS_STR];
    __shared__ uint32_t Ws[128 * GS_STR];

    const int b  = blockIdx.z >> 2;
    const int kh = blockIdx.z & 3;
    const int m0 = blockIdx.y * 128;
    const int n0 = blockIdx.x * 128;
    const int tid = threadIdx.x;
    const int lane = tid & 31;
    const int warp = tid >> 5;
    const int warp_m = warp >> 2;
    const int warp_n = warp & 3;
    const int qd = lane >> 2;
    const int qq = lane & 3;

    const int lr = tid >> 1;
    const int lc = (tid & 1) * 16;

    const uint32_t* Ap = (const uint32_t*)QK + (size_t)(b * SEQ + m0 + lr) * 512 + kh * HD + lc;
    const uint32_t* Wp = (const uint32_t*)QK + (size_t)(b * SEQ + n0 + lr) * 512 + 256 + kh * HD + lc;
    uint32_t* Asd = &As[lr * GS_STR + lc];
    uint32_t* Wsd = &Ws[lr * GS_STR + lc];

    float acc[4][4][4];
#pragma unroll
    for (int mf = 0; mf < 4; mf++)
#pragma unroll
        for (int nf = 0; nf < 4; nf++)
#pragma unroll
            for (int c = 0; c < 4; c++) acc[mf][nf][c] = 0.f;

    uint4 av[4], wv[4];
#pragma unroll
    for (int i = 0; i < 4; i++) {
        av[i] = *(const uint4*)(Ap + i * 4);
        wv[i] = *(const uint4*)(Wp + i * 4);
    }

#pragma unroll
    for (int k0 = 0; k0 < HD; k0 += 32) {
        __syncthreads();
#pragma unroll
        for (int i = 0; i < 4; i++) {
            *(uint4*)(Asd + i * 4) = av[i];
            *(uint4*)(Wsd + i * 4) = wv[i];
        }
        __syncthreads();

        if (k0 + 32 < HD) {
#pragma unroll
            for (int i = 0; i < 4; i++) {
                av[i] = *(const uint4*)(Ap + k0 + 32 + i * 4);
                wv[i] = *(const uint4*)(Wp + k0 + 32 + i * 4);
            }
        }

#pragma unroll
        for (int kk = 0; kk < 32; kk += 8) {
            uint32_t a[4][4];
#pragma unroll
            for (int mf = 0; mf < 4; mf++) {
                const int base = warp_m * 64 + mf * 16 + qd;
                a[mf][0] = As[base * GS_STR + kk + qq];
                a[mf][1] = As[(base + 8) * GS_STR + kk + qq];
                a[mf][2] = As[base * GS_STR + kk + qq + 4];
                a[mf][3] = As[(base + 8) * GS_STR + kk + qq + 4];
            }
#pragma unroll
            for (int nf = 0; nf < 4; nf++) {
                const int col = warp_n * 32 + nf * 8 + qd;
                uint32_t bfr[2];
                bfr[0] = Ws[col * GS_STR + kk + qq];
                bfr[1] = Ws[col * GS_STR + kk + qq + 4];
#pragma unroll
                for (int mf = 0; mf < 4; mf++)
                    mma_tf32(acc[mf][nf], a[mf], bfr);
            }
        }
    }

    float* Cp = GL + (size_t)blockIdx.z * SEQ * SEQ;
#pragma unroll
    for (int mf = 0; mf < 4; mf++) {
        const int row0 = m0 + warp_m * 64 + mf * 16 + qd;
        const int row1 = row0 + 8;
#pragma unroll
        for (int nf = 0; nf < 4; nf++) {
            const int col = n0 + warp_n * 32 + nf * 8 + 2 * qq;
            float2 o0, o1;
            o0.x = acc[mf][nf][0]; o0.y = acc[mf][nf][1];
            o1.x = acc[mf][nf][2]; o1.y = acc[mf][nf][3];
            *(float2*)&Cp[(size_t)row0 * SEQ + col] = o0;
            *(float2*)&Cp[(size_t)row1 * SEQ + col] = o1;
        }
    }
}

// ---------------------------------------------------------------------------
// Kernel B: mix + softmax + AV. 2 heads/CTA (256 thr, 2 CTAs/SM).
// Register-resident P. V stored TRANSPOSED in smem: Vt[d][j] -> AV B-frags
// are single LDS.64 (adjacent j pair), conflict-free at VT_STR=72.
// ---------------------------------------------------------------------------
#define HPC    2
#define SG_STR 72
#define SG_K   (64 * SG_STR)
#define VT_STR 72

__global__ void __launch_bounds__(256, 2) fish_mix_attn(const float* __restrict__ mixl,
                                                        const float* __restrict__ GL,
                                                        float* __restrict__ ctx)
{
    extern __shared__ float sm[];
    float* Sg    = sm;                          // [4k][64][SG_STR], shared by heads
    float* VtAll = Sg + 4 * SG_K;               // [2 heads][64 d][VT_STR]

    const int i0   = blockIdx.x * 64;
    const int b    = blockIdx.z;
    const int tid  = threadIdx.x;
    const int hh   = tid >> 7;
    const int t    = tid & 127;
    const int h    = blockIdx.y * HPC + hh;
    const int lane = tid & 31;
    const int w4   = t >> 5;
    const int qd   = lane >> 2;
    const int qq   = lane & 3;
    const int bar_id = hh + 1;

    const int row0 = 16 * w4 + qd;
    const int row1 = row0 + 8;

    float* Vt = VtAll + hh * 64 * VT_STR;
    const float* gvt = g_vt + (size_t)(b * NH + h) * HD * SEQ;   // [d][j]

    const int gc = (tid & 15) * 4;
    const int gr = tid >> 4;
    // V copy slots (per head, half-tile = 32 j-cols x 64 d-rows):
    const int vjc = (t & 7) * 4;                // j chunk within half (0..28)
    const int vdr = t >> 3;                     // d row 0..15, step 16 x4
    const uint32_t SgA = (uint32_t)__cvta_generic_to_shared(Sg);
    const uint32_t VtA = (uint32_t)__cvta_generic_to_shared(Vt);

    // Prologue: group1 = Sg(0) + Vlow(0); group2 = Vhigh(0)
#pragma unroll
    for (int i = 0; i < 16; i++) {
        const int r = gr + 16 * i;
        const int k = r >> 6, rr = r & 63;
        cp16(SgA + (uint32_t)((k * 64 + rr) * SG_STR + gc) * 4,
             &GL[((size_t)(b * KG + k) * SEQ + i0 + rr) * SEQ + 0 + gc]);
    }
#pragma unroll
    for (int i = 0; i < 4; i++) {
        const int d = vdr + 16 * i;
        cp16(VtA + (uint32_t)(d * VT_STR + vjc) * 4, &gvt[(size_t)d * SEQ + 0 + vjc]);
    }
    cp_commit();
#pragma unroll
    for (int i = 0; i < 4; i++) {
        const int d = vdr + 16 * i;
        cp16(VtA + (uint32_t)(d * VT_STR + 32 + vjc) * 4, &gvt[(size_t)d * SEQ + 32 + vjc]);
    }
    cp_commit();

    // mixw = softmax(mix_logits[h,:]) * HEAD_DIM^-0.5
    float ml0 = mixl[h * KG + 0], ml1 = mixl[h * KG + 1];
    float ml2 = mixl[h * KG + 2], ml3 = mixl[h * KG + 3];
    float mm = fmaxf(fmaxf(ml0, ml1), fmaxf(ml2, ml3));
    float e0 = expf(ml0 - mm), e1 = expf(ml1 - mm);
    float e2 = expf(ml2 - mm), e3 = expf(ml3 - mm);
    float inv_es = 0.125f / (e0 + e1 + e2 + e3);
    const float mw0 = e0 * inv_es, mw1 = e1 * inv_es;
    const float mw2 = e2 * inv_es, mw3 = e3 * inv_es;

    float O[8][4];
#pragma unroll
    for (int nt = 0; nt < 8; nt++)
#pragma unroll
        for (int c = 0; c < 4; c++) O[nt][c] = 0.f;
    float m_0 = -INFINITY, m_1 = -INFINITY, l_0 = 0.f, l_1 = 0.f;

    const uint32_t* Vtu = (const uint32_t*)Vt;
    const float* mixbase = Sg + row0 * SG_STR + 2 * qq;

    for (int j0 = 0; j0 < SEQ; j0 += 64) {
        const bool more = (j0 + 64 < SEQ);

        cp_wait1();
        __syncthreads();

        // ---- mix ----
        float S[8][4];
#pragma unroll
        for (int nt = 0; nt < 8; nt++) {
            const float* p = mixbase + nt * 8;
            float2 a0 = *(const float2*)(p);
            float2 a1 = *(const float2*)(p + 8 * SG_STR);
            float2 b0 = *(const float2*)(p + SG_K);
            float2 b1 = *(const float2*)(p + SG_K + 8 * SG_STR);
            float2 c0 = *(const float2*)(p + 2 * SG_K);
            float2 c1 = *(const float2*)(p + 2 * SG_K + 8 * SG_STR);
            float2 d0 = *(const float2*)(p + 3 * SG_K);
            float2 d1 = *(const float2*)(p + 3 * SG_K + 8 * SG_STR);
            S[nt][0] = mw0 * a0.x + mw1 * b0.x + mw2 * c0.x + mw3 * d0.x;
            S[nt][1] = mw0 * a0.y + mw1 * b0.y + mw2 * c0.y + mw3 * d0.y;
            S[nt][2] = mw0 * a1.x + mw1 * b1.x + mw2 * c1.x + mw3 * d1.x;
            S[nt][3] = mw0 * a1.y + mw1 * b1.y + mw2 * c1.y + mw3 * d1.y;
        }
        __syncthreads();

        if (more) {
#pragma unroll
            for (int i = 0; i < 16; i++) {
                const int r = gr + 16 * i;
                const int k = r >> 6, rr = r & 63;
                cp16(SgA + (uint32_t)((k * 64 + rr) * SG_STR + gc) * 4,
                     &GL[((size_t)(b * KG + k) * SEQ + i0 + rr) * SEQ + j0 + 64 + gc]);
            }
            cp_commit();
        }

        // ---- warp-local online softmax ----
        float mx0 = fmaxf(S[0][0], S[0][1]), mx1 = fmaxf(S[0][2], S[0][3]);
#pragma unroll
        for (int nt = 1; nt < 8; nt++) {
            mx0 = fmaxf(mx0, fmaxf(S[nt][0], S[nt][1]));
            mx1 = fmaxf(mx1, fmaxf(S[nt][2], S[nt][3]));
        }
        mx0 = fmaxf(mx0, __shfl_xor_sync(0xffffffffu, mx0, 1));
        mx0 = fmaxf(mx0, __shfl_xor_sync(0xffffffffu, mx0, 2));
        mx1 = fmaxf(mx1, __shfl_xor_sync(0xffffffffu, mx1, 1));
        mx1 = fmaxf(mx1, __shfl_xor_sync(0xffffffffu, mx1, 2));
        const float mn0 = fmaxf(m_0, mx0), mn1 = fmaxf(m_1, mx1);
        const float corr0 = __expf(m_0 - mn0), corr1 = __expf(m_1 - mn1);
        m_0 = mn0; m_1 = mn1;

        uint32_t P[8][4];
        float rs0 = 0.f, rs1 = 0.f;
#pragma unroll
        for (int nt = 0; nt < 8; nt++) {
            const float p0 = __expf(S[nt][0] - mn0);
            const float p1 = __expf(S[nt][1] - mn0);
            const float p2 = __expf(S[nt][2] - mn1);
            const float p3 = __expf(S[nt][3] - mn1);
            rs0 += p0 + p1; rs1 += p2 + p3;
            P[nt][0] = f2tf(p0); P[nt][1] = f2tf(p2);
            P[nt][2] = f2tf(p1); P[nt][3] = f2tf(p3);
            O[nt][0] *= corr0; O[nt][1] *= corr0;
            O[nt][2] *= corr1; O[nt][3] *= corr1;
        }
        rs0 += __shfl_xor_sync(0xffffffffu, rs0, 1);
        rs0 += __shfl_xor_sync(0xffffffffu, rs0, 2);
        rs1 += __shfl_xor_sync(0xffffffffu, rs1, 1);
        rs1 += __shfl_xor_sync(0xffffffffu, rs1, 2);
        l_0 = l_0 * corr0 + rs0;
        l_1 = l_1 * corr1 + rs1;

        // ---- O += P V, low half (kg 0..3; Vt[d][jr..jr+1] = one LDS.64) ----
#pragma unroll
        for (int kg = 0; kg < 4; kg++) {
            const int jr = kg * 8 + 2 * qq;
#pragma unroll
            for (int nt = 0; nt < 8; nt++) {
                const int d = nt * 8 + qd;
                uint2 bf2 = *(const uint2*)(Vtu + d * VT_STR + jr);
                uint32_t bf[2] = {bf2.x, bf2.y};
                mma_tf32(O[nt], P[kg], bf);
            }
        }

        if (more) cp_wait1(); else cp_wait_all();
        bar_named(bar_id, 128);
        if (more) {
#pragma unroll
            for (int i = 0; i < 4; i++) {
                const int d = vdr + 16 * i;
                cp16(VtA + (uint32_t)(d * VT_STR + vjc) * 4,
                     &gvt[(size_t)d * SEQ + j0 + 64 + vjc]);
            }
            cp_commit();
        }

        // ---- O += P V, high half (kg 4..7) ----
#pragma unroll
        for (int kg = 4; kg < 8; kg++) {
            const int jr = kg * 8 + 2 * qq;
#pragma unroll
            for (int nt = 0; nt < 8; nt++) {
                const int d = nt * 8 + qd;
                uint2 bf2 = *(const uint2*)(Vtu + d * VT_STR + jr);
                uint32_t bf[2] = {bf2.x, bf2.y};
                mma_tf32(O[nt], P[kg], bf);
            }
        }

        bar_named(bar_id, 128);
        if (more) {
#pragma unroll
            for (int i = 0; i < 4; i++) {
                const int d = vdr + 16 * i;
                cp16(VtA + (uint32_t)(d * VT_STR + 32 + vjc) * 4,
                     &gvt[(size_t)d * SEQ + j0 + 64 + 32 + vjc]);
            }
            cp_commit();
        }
    }

    // Epilogue: normalize, write ctx (B,N,768) fp32
    const float inv0 = 1.f / l_0, inv1 = 1.f / l_1;
    const size_t r0off = ((size_t)(b * SEQ + i0 + row0)) * DIM + h * HD;
    const size_t r1off = ((size_t)(b * SEQ + i0 + row1)) * DIM + h * HD;
#pragma unroll
    for (int nt = 0; nt < 8; nt++) {
        const int col = nt * 8 + 2 * qq;
        float2 o0; o0.x = O[nt][0] * inv0; o0.y = O[nt][1] * inv0;
        float2 o1; o1.x = O[nt][2] * inv1; o1.y = O[nt][3] * inv1;
        *(float2*)&ctx[r0off + col] = o0;
        *(float2*)&ctx[r1off + col] = o1;
    }
}

// ---------------------------------------------------------------------------
// Launch
// ---------------------------------------------------------------------------
extern "C" void kernel_launch(void* const* d_in, const int* in_sizes, int n_in,
                              void* d_out, int out_size)
{
    const float* x      = (const float*)d_in[0];
    const float* w_qkv  = (const float*)d_in[1];
    const float* mixl   = (const float*)d_in[2];
    const float* w_v    = (const float*)d_in[3];
    const float* w_proj = (const float*)d_in[4];
    const float* b_proj = (const float*)d_in[5];
    float* out = (float*)d_out;

    float *qk, *vt, *ctx, *gl;
    cudaGetSymbolAddress((void**)&qk,  g_qk);
    cudaGetSymbolAddress((void**)&vt,  g_vt);
    cudaGetSymbolAddress((void**)&ctx, g_ctx);
    cudaGetSymbolAddress((void**)&gl,  g_gl);

    const int attn_smem = (4 * SG_K + HPC * 64 * VT_STR) * (int)sizeof(float);
    cudaFuncSetAttribute(fish_mix_attn, cudaFuncAttributeMaxDynamicSharedMemorySize, attn_smem);

    // 1) qk = x @ w_qkv[0:512]^T  -> tf32 bits
    tf32_gemm_nt<512, 1, false><<<dim3(4, 64), 256>>>(x, w_qkv, nullptr, qk);
    // 2) v = x @ w_v^T            -> tf32 bits, TRANSPOSED layout [b,h,d,j]
    tf32_gemm_nt<768, 2, false><<<dim3(6, 64), 256>>>(x, w_v, nullptr, vt);
    // A) global logits per (b, k-head): gl = q_k . k_k^T  (fp32 raw)
    gl_gemm<<<dim3(8, 8, BB * KG), 256>>>(qk, gl);
    // B) mix + softmax + AV, 2 heads/CTA, register P, transposed-V LDS.64
    fish_mix_attn<<<dim3(SEQ / 64, NH / HPC, BB), HPC * 128, attn_smem>>>(mixl, gl, ctx);
    // 4) out = ctx @ w_proj^T + b_proj (fp32 out)
    tf32_gemm_nt<768, 0, true><<<dim3(6, 64), 256>>>(ctx, w_proj, b_proj, out);
}